// round 16
// baseline (speedup 1.0000x reference)
#include <cuda_runtime.h>
#include <math.h>

#define Nn 1024
#define Ff 64
#define ALPHA 0.2f

// scratch
__device__ __align__(16) float g_Wh[Nn * Ff];
__device__ float g_e1[Nn];
__device__ float g_e2[Nn];

// ---------------------------------------------------------------------------
// k1: Wh = h @ W ; e1 = Wh@a1 ; e2 = Wh@a2. grid 512 (2 rows/block).
// Issues griddepcontrol.launch_dependents early (PDL).
// ---------------------------------------------------------------------------
__global__ __launch_bounds__(256) void gat_k1(const float* __restrict__ h,
                                              const float* __restrict__ W,
                                              const float* __restrict__ a) {
    __shared__ float Ws[Ff * Ff];
    __shared__ float hs[2 * Ff];
    __shared__ float a1s[Ff], a2s[Ff];
    __shared__ float es1[4], es2[4];
    int t = threadIdx.x;
    int row0 = blockIdx.x * 2;

    asm volatile("griddepcontrol.launch_dependents;" ::: "memory");

#pragma unroll
    for (int k = 0; k < 4; k++)
        ((float4*)Ws)[t + k * 256] = ((const float4*)W)[t + k * 256];
    if (t < 128) hs[t] = h[row0 * Ff + t];
    if (t < Ff) { a1s[t] = a[t]; a2s[t] = a[Ff + t]; }
    __syncthreads();

    if (t < 128) {
        int row_i = t >> 6;     // 0..1
        int ff = t & 63;
        float acc = 0.f;
#pragma unroll
        for (int k = 0; k < Ff; k++)
            acc += hs[row_i * Ff + k] * Ws[k * Ff + ff];
        int row = row0 + row_i;
        g_Wh[row * Ff + ff] = acc;

        float p1 = acc * a1s[ff];
        float p2 = acc * a2s[ff];
#pragma unroll
        for (int o = 16; o; o >>= 1) {
            p1 += __shfl_xor_sync(0xffffffffu, p1, o);
            p2 += __shfl_xor_sync(0xffffffffu, p2, o);
        }
        int w = t >> 5;         // 0..3
        if ((t & 31) == 0) { es1[w] = p1; es2[w] = p2; }
    }
    __syncthreads();
    if (t < 2) {
        g_e1[row0 + t] = es1[2 * t] + es1[2 * t + 1];
        g_e2[row0 + t] = es2[2 * t] + es2[2 * t + 1];
    }
}

// ---------------------------------------------------------------------------
// k2: fused attention, out = elu( (P@Wh)/rowsum ), unnormalized softmax.
// grid 256 (4 rows/block), 256 threads, 2 CTA/SM, 128 regs.
// Thread (fi = t&7, jg = t>>3): 4 rows x 8 features (Wh columns fi, fi+8).
// Wh LDG.128 prefetched at DISTANCE 2 (3-buffer ring) so ~250-cyc L2
// latency is fully covered by two iteration epochs. ALL p-tiles upfront,
// barrier-free GEMM, red overlays ps, 3 barriers, PDL adj prologue.
// ---------------------------------------------------------------------------
__global__ __launch_bounds__(256, 2) void gat_k2(const int* __restrict__ adj,
                                                 float* __restrict__ out) {
    __shared__ __align__(16) float sbuf[8448];  // ps[0,8192) ∪ red[0,8448)
    __shared__ float wpart[8][4];
    __shared__ float dfin[4];

    int t = threadIdx.x;
    int r0 = blockIdx.x * 4;
    int fi = t & 7;
    int jg = t >> 3;

    // ---- PDL prologue: adj loads (independent of k1) ----
    int av[4][4];
#pragma unroll
    for (int c = 0; c < 4; c++) {
        const int* ac = adj + c * 256 + t;
#pragma unroll
        for (int r = 0; r < 4; r++)
            av[c][r] = __ldg(ac + (size_t)(r0 + r) * Nn);
    }

    asm volatile("griddepcontrol.wait;" ::: "memory");

    float e2v[4];
#pragma unroll
    for (int c = 0; c < 4; c++)
        e2v[c] = __ldg(&g_e2[c * 256 + t]);
    float e1r0 = __ldg(&g_e1[r0 + 0]);
    float e1r1 = __ldg(&g_e1[r0 + 1]);
    float e1r2 = __ldg(&g_e1[r0 + 2]);
    float e1r3 = __ldg(&g_e1[r0 + 3]);

    // ---- ALL p-tiles upfront: thread t owns j = c*256 + t, all 4 rows ----
    float* ps = sbuf;
    float d0 = 0.f, d1 = 0.f, d2 = 0.f, d3 = 0.f;
#pragma unroll
    for (int c = 0; c < 4; c++) {
        float e2 = e2v[c];
        float s0 = e1r0 + e2; s0 = (s0 > 0.f) ? s0 : ALPHA * s0;
        float s1 = e1r1 + e2; s1 = (s1 > 0.f) ? s1 : ALPHA * s1;
        float s2 = e1r2 + e2; s2 = (s2 > 0.f) ? s2 : ALPHA * s2;
        float s3 = e1r3 + e2; s3 = (s3 > 0.f) ? s3 : ALPHA * s3;
        float p0 = (av[c][0] > 0) ? __expf(s0) : 0.f;
        float p1 = (av[c][1] > 0) ? __expf(s1) : 0.f;
        float p2 = (av[c][2] > 0) ? __expf(s2) : 0.f;
        float p3 = (av[c][3] > 0) ? __expf(s3) : 0.f;
        d0 += p0; d1 += p1; d2 += p2; d3 += p3;
        int j = c * 256 + t;
        *(float4*)&ps[j * 8]     = make_float4(p0, p0, p1, p1);
        *(float4*)&ps[j * 8 + 4] = make_float4(p2, p2, p3, p3);
    }

    // ---- dsum: warp-reduce -> wpart ----
#pragma unroll
    for (int o = 16; o; o >>= 1) {
        d0 += __shfl_xor_sync(0xffffffffu, d0, o);
        d1 += __shfl_xor_sync(0xffffffffu, d1, o);
        d2 += __shfl_xor_sync(0xffffffffu, d2, o);
        d3 += __shfl_xor_sync(0xffffffffu, d3, o);
    }
    if ((t & 31) == 0) {
        int w = t >> 5;
        wpart[w][0] = d0; wpart[w][1] = d1; wpart[w][2] = d2; wpart[w][3] = d3;
    }

    // ---- prefetch Wh steps 0 and 1 (two columns each): 3-buffer ring ----
    const ulonglong2* WhL = (const ulonglong2*)g_Wh;
    ulonglong2 wbuf[3][2];
    wbuf[0][0] = WhL[(size_t)jg * 16 + fi];
    wbuf[0][1] = WhL[(size_t)jg * 16 + fi + 8];
    wbuf[1][0] = WhL[(size_t)(32 + jg) * 16 + fi];
    wbuf[1][1] = WhL[(size_t)(32 + jg) * 16 + fi + 8];

    unsigned long long a0[8] = {0,0,0,0,0,0,0,0};   // col fi:   rows x {f01,f23}
    unsigned long long a1[8] = {0,0,0,0,0,0,0,0};   // col fi+8
    __syncthreads();                       // (1) ps + wpart complete

    // ---- GEMM: 32 j-steps, barrier-free, distance-2 prefetch ring ----
#pragma unroll
    for (int k = 0; k < 32; k++) {
        int cb = k % 3;
        if (k < 30) {
            int nb = (k + 2) % 3;
            int jn = (k + 2) * 32 + jg;
            wbuf[nb][0] = WhL[(size_t)jn * 16 + fi];
            wbuf[nb][1] = WhL[(size_t)jn * 16 + fi + 8];
        }
        int j = k * 32 + jg;
        ulonglong2 pA = *(const ulonglong2*)&ps[j * 8];
        ulonglong2 pB = *(const ulonglong2*)&ps[j * 8 + 4];
        ulonglong2 w0 = wbuf[cb][0];
        ulonglong2 w1 = wbuf[cb][1];
        asm("fma.rn.f32x2 %0,%1,%2,%0;" : "+l"(a0[0]) : "l"(pA.x), "l"(w0.x));
        asm("fma.rn.f32x2 %0,%1,%2,%0;" : "+l"(a0[1]) : "l"(pA.x), "l"(w0.y));
        asm("fma.rn.f32x2 %0,%1,%2,%0;" : "+l"(a0[2]) : "l"(pA.y), "l"(w0.x));
        asm("fma.rn.f32x2 %0,%1,%2,%0;" : "+l"(a0[3]) : "l"(pA.y), "l"(w0.y));
        asm("fma.rn.f32x2 %0,%1,%2,%0;" : "+l"(a0[4]) : "l"(pB.x), "l"(w0.x));
        asm("fma.rn.f32x2 %0,%1,%2,%0;" : "+l"(a0[5]) : "l"(pB.x), "l"(w0.y));
        asm("fma.rn.f32x2 %0,%1,%2,%0;" : "+l"(a0[6]) : "l"(pB.y), "l"(w0.x));
        asm("fma.rn.f32x2 %0,%1,%2,%0;" : "+l"(a0[7]) : "l"(pB.y), "l"(w0.y));
        asm("fma.rn.f32x2 %0,%1,%2,%0;" : "+l"(a1[0]) : "l"(pA.x), "l"(w1.x));
        asm("fma.rn.f32x2 %0,%1,%2,%0;" : "+l"(a1[1]) : "l"(pA.x), "l"(w1.y));
        asm("fma.rn.f32x2 %0,%1,%2,%0;" : "+l"(a1[2]) : "l"(pA.y), "l"(w1.x));
        asm("fma.rn.f32x2 %0,%1,%2,%0;" : "+l"(a1[3]) : "l"(pA.y), "l"(w1.y));
        asm("fma.rn.f32x2 %0,%1,%2,%0;" : "+l"(a1[4]) : "l"(pB.x), "l"(w1.x));
        asm("fma.rn.f32x2 %0,%1,%2,%0;" : "+l"(a1[5]) : "l"(pB.x), "l"(w1.y));
        asm("fma.rn.f32x2 %0,%1,%2,%0;" : "+l"(a1[6]) : "l"(pB.y), "l"(w1.x));
        asm("fma.rn.f32x2 %0,%1,%2,%0;" : "+l"(a1[7]) : "l"(pB.y), "l"(w1.y));
    }
    __syncthreads();                       // (2) ps reads done -> red overlay

    // ---- dfin ----
    if (t < 4) {
        float dd = 0.f;
#pragma unroll
        for (int w2 = 0; w2 < 8; w2++) dd += wpart[w2][t];
        dfin[t] = dd;
    }

    // ---- write register tiles to red (overlays ps) ----
    float* red = sbuf;
#pragma unroll
    for (int ii = 0; ii < 4; ii++) {
        float2 lo0 = *(float2*)&a0[ii * 2];
        float2 hi0 = *(float2*)&a0[ii * 2 + 1];
        *(float4*)&red[jg * 264 + ii * 64 + fi * 4] =
            make_float4(lo0.x, lo0.y, hi0.x, hi0.y);
        float2 lo1 = *(float2*)&a1[ii * 2];
        float2 hi1 = *(float2*)&a1[ii * 2 + 1];
        *(float4*)&red[jg * 264 + ii * 64 + 32 + fi * 4] =
            make_float4(lo1.x, lo1.y, hi1.x, hi1.y);
    }
    __syncthreads();                       // (3)

    // ---- final: thread t owns output element t of the 4x64 tile ----
    {
        float val = 0.f;
#pragma unroll
        for (int g = 0; g < 32; g++)
            val += red[g * 264 + t];
        int oii = t >> 6;
        int of  = t & 63;
        float r = val / dfin[oii];
        r = (r > 0.f) ? r : expm1f(r);
        out[(size_t)(r0 + oii) * Ff + of] = r;
    }
}

// ---------------------------------------------------------------------------
extern "C" void kernel_launch(void* const* d_in, const int* in_sizes, int n_in,
                              void* d_out, int out_size) {
    const float* h   = (const float*)d_in[0];
    const int*   adj = (const int*)d_in[1];
    const float* W   = (const float*)d_in[2];
    const float* a   = (const float*)d_in[3];
    float* out = (float*)d_out;

    gat_k1<<<512, 256>>>(h, W, a);

    cudaLaunchConfig_t cfg = {};
    cfg.gridDim  = dim3(256, 1, 1);
    cfg.blockDim = dim3(256, 1, 1);
    cfg.dynamicSmemBytes = 0;
    cfg.stream = 0;
    cudaLaunchAttribute attrs[1];
    attrs[0].id = cudaLaunchAttributeProgrammaticStreamSerialization;
    attrs[0].val.programmaticStreamSerializationAllowed = 1;
    cfg.attrs = attrs;
    cfg.numAttrs = 1;
    cudaLaunchKernelEx(&cfg, gat_k2, adj, (float*)out);
}

// round 17
// speedup vs baseline: 1.0151x; 1.0151x over previous
#include <cuda_runtime.h>
#include <math.h>

#define Nn 1024
#define Ff 64
#define ALPHA 0.2f

// scratch
__device__ __align__(16) float g_Wh[Nn * Ff];
__device__ float g_e1[Nn];
__device__ float g_e2[Nn];

// ---------------------------------------------------------------------------
// k1: Wh = h @ W ; e1 = Wh@a1 ; e2 = Wh@a2. grid 512 (2 rows/block).
// Issues griddepcontrol.launch_dependents early (PDL).
// ---------------------------------------------------------------------------
__global__ __launch_bounds__(256) void gat_k1(const float* __restrict__ h,
                                              const float* __restrict__ W,
                                              const float* __restrict__ a) {
    __shared__ float Ws[Ff * Ff];
    __shared__ float hs[2 * Ff];
    __shared__ float a1s[Ff], a2s[Ff];
    __shared__ float es1[4], es2[4];
    int t = threadIdx.x;
    int row0 = blockIdx.x * 2;

    asm volatile("griddepcontrol.launch_dependents;" ::: "memory");

#pragma unroll
    for (int k = 0; k < 4; k++)
        ((float4*)Ws)[t + k * 256] = ((const float4*)W)[t + k * 256];
    if (t < 128) hs[t] = h[row0 * Ff + t];
    if (t < Ff) { a1s[t] = a[t]; a2s[t] = a[Ff + t]; }
    __syncthreads();

    if (t < 128) {
        int row_i = t >> 6;     // 0..1
        int ff = t & 63;
        float acc = 0.f;
#pragma unroll
        for (int k = 0; k < Ff; k++)
            acc += hs[row_i * Ff + k] * Ws[k * Ff + ff];
        int row = row0 + row_i;
        g_Wh[row * Ff + ff] = acc;

        float p1 = acc * a1s[ff];
        float p2 = acc * a2s[ff];
#pragma unroll
        for (int o = 16; o; o >>= 1) {
            p1 += __shfl_xor_sync(0xffffffffu, p1, o);
            p2 += __shfl_xor_sync(0xffffffffu, p2, o);
        }
        int w = t >> 5;         // 0..3
        if ((t & 31) == 0) { es1[w] = p1; es2[w] = p2; }
    }
    __syncthreads();
    if (t < 2) {
        g_e1[row0 + t] = es1[2 * t] + es1[2 * t + 1];
        g_e2[row0 + t] = es2[2 * t] + es2[2 * t + 1];
    }
}

#define FMA2(acc, p, w) \
    asm("fma.rn.f32x2 %0,%1,%2,%0;" : "+l"(acc) : "l"(p), "l"(w))

// ---------------------------------------------------------------------------
// k2: fused attention, out = elu( (P@Wh)/rowsum ), unnormalized softmax.
// grid 128 (8 rows/block — HALVES chip-wide Wh L2 traffic to 32MB and
// per-SM wavefronts per MAC), 512 threads, 1 CTA/SM, <=128 regs.
// Thread (fi = t&15, jg = t>>4): 8 rows x 4 features. Per j-step:
// 1 LDG.128 (Wh, distance-2 ring) + 4 broadcast LDS.128 (p dup-pairs)
// feed 16 fma.f32x2 (32 MACs). ALL p-tiles upfront in 64KB dynamic SMEM;
// barrier-free GEMM; in-warp shfl reduction of jg-pairs (32 splits -> 16);
// red (33KB) overlays ps. 3 barriers. PDL adj prologue overlaps k1.
// ---------------------------------------------------------------------------
__global__ __launch_bounds__(512, 1) void gat_k2(const int* __restrict__ adj,
                                                 float* __restrict__ out) {
    extern __shared__ __align__(16) float sbuf[];   // ps 16384 fl ∪ red 8320 fl
    __shared__ float wpart[16][8];
    __shared__ float dfin[8];

    int t = threadIdx.x;
    int r0 = blockIdx.x * 8;
    int fi = t & 15;
    int jg = t >> 4;                 // 0..31
    int lane = t & 31, w = t >> 5;   // warp 0..15

    // ---- PDL prologue: adj loads (independent of k1) ----
    int av[2][8];
#pragma unroll
    for (int c = 0; c < 2; c++) {
        const int* ac = adj + c * 512 + t;
#pragma unroll
        for (int r = 0; r < 8; r++)
            av[c][r] = __ldg(ac + (size_t)(r0 + r) * Nn);
    }

    asm volatile("griddepcontrol.wait;" ::: "memory");

    float e2v0 = __ldg(&g_e2[t]);
    float e2v1 = __ldg(&g_e2[t + 512]);
    float e1r[8];
#pragma unroll
    for (int r = 0; r < 8; r++) e1r[r] = __ldg(&g_e1[r0 + r]);

    // ---- ALL p-tiles upfront: thread t owns j in {t, t+512}, 8 rows ----
    float* ps = sbuf;
    float d[8] = {0.f, 0.f, 0.f, 0.f, 0.f, 0.f, 0.f, 0.f};
#pragma unroll
    for (int c = 0; c < 2; c++) {
        int j = c * 512 + t;
        float e2 = c ? e2v1 : e2v0;
        float p[8];
#pragma unroll
        for (int r = 0; r < 8; r++) {
            float s = e1r[r] + e2;
            s = (s > 0.f) ? s : ALPHA * s;
            p[r] = (av[c][r] > 0) ? __expf(s) : 0.f;
            d[r] += p[r];
        }
        float* bp = &ps[j * 16];
        *(float4*)(bp + 0)  = make_float4(p[0], p[0], p[1], p[1]);
        *(float4*)(bp + 4)  = make_float4(p[2], p[2], p[3], p[3]);
        *(float4*)(bp + 8)  = make_float4(p[4], p[4], p[5], p[5]);
        *(float4*)(bp + 12) = make_float4(p[6], p[6], p[7], p[7]);
    }

    // ---- dsum: warp-reduce -> wpart ----
#pragma unroll
    for (int o = 16; o; o >>= 1) {
#pragma unroll
        for (int r = 0; r < 8; r++)
            d[r] += __shfl_xor_sync(0xffffffffu, d[r], o);
    }
    if (lane == 0) {
#pragma unroll
        for (int r = 0; r < 8; r++) wpart[w][r] = d[r];
    }

    // ---- Wh distance-2 prefetch ring ----
    const ulonglong2* WhL = (const ulonglong2*)g_Wh;
    ulonglong2 wring[3];
    wring[0] = WhL[(size_t)jg * 16 + fi];
    wring[1] = WhL[(size_t)(32 + jg) * 16 + fi];

    unsigned long long acc[16];
#pragma unroll
    for (int i = 0; i < 16; i++) acc[i] = 0ull;
    __syncthreads();                       // (1) ps + wpart complete

    // ---- GEMM: 32 j-steps, barrier-free ----
#pragma unroll
    for (int k = 0; k < 32; k++) {
        int cb = k % 3;
        if (k < 30)
            wring[(k + 2) % 3] = WhL[(size_t)((k + 2) * 32 + jg) * 16 + fi];
        int j = k * 32 + jg;
        const float* bp = &ps[j * 16];
        ulonglong2 pA = *(const ulonglong2*)(bp);
        ulonglong2 pB = *(const ulonglong2*)(bp + 4);
        ulonglong2 pC = *(const ulonglong2*)(bp + 8);
        ulonglong2 pD = *(const ulonglong2*)(bp + 12);
        ulonglong2 wv = wring[cb];
        FMA2(acc[0],  pA.x, wv.x); FMA2(acc[1],  pA.x, wv.y);
        FMA2(acc[2],  pA.y, wv.x); FMA2(acc[3],  pA.y, wv.y);
        FMA2(acc[4],  pB.x, wv.x); FMA2(acc[5],  pB.x, wv.y);
        FMA2(acc[6],  pB.y, wv.x); FMA2(acc[7],  pB.y, wv.y);
        FMA2(acc[8],  pC.x, wv.x); FMA2(acc[9],  pC.x, wv.y);
        FMA2(acc[10], pC.y, wv.x); FMA2(acc[11], pC.y, wv.y);
        FMA2(acc[12], pD.x, wv.x); FMA2(acc[13], pD.x, wv.y);
        FMA2(acc[14], pD.y, wv.x); FMA2(acc[15], pD.y, wv.y);
    }
    __syncthreads();                       // (2) ps reads done -> red overlay OK

    // ---- in-warp jg-pair reduction (lane^16 has the partner jg) ----
    float2 fr[16];
#pragma unroll
    for (int i = 0; i < 16; i++) {
        float2 v = *(float2*)&acc[i];
        v.x += __shfl_xor_sync(0xffffffffu, v.x, 16);
        v.y += __shfl_xor_sync(0xffffffffu, v.y, 16);
        fr[i] = v;
    }

    // ---- dfin ----
    if (t < 8) {
        float dd = 0.f;
#pragma unroll
        for (int ww = 0; ww < 16; ww++) dd += wpart[ww][t];
        dfin[t] = dd;
    }

    // ---- write 16 warp-splits to red (overlays ps) ----
    float* red = sbuf;
    if (lane < 16) {
#pragma unroll
        for (int r = 0; r < 8; r++)
            *(float4*)&red[w * 520 + r * 64 + fi * 4] =
                make_float4(fr[r * 2].x, fr[r * 2].y,
                            fr[r * 2 + 1].x, fr[r * 2 + 1].y);
    }
    __syncthreads();                       // (3)

    // ---- final: thread t owns output element t of the 8x64 tile ----
    {
        float val = 0.f;
#pragma unroll
        for (int g = 0; g < 16; g++)
            val += red[g * 520 + t];
        int r = t >> 6;
        int f = t & 63;
        float rr = val / dfin[r];
        rr = (rr > 0.f) ? rr : expm1f(rr);
        out[(size_t)(r0 + r) * Ff + f] = rr;
    }
}

// ---------------------------------------------------------------------------
extern "C" void kernel_launch(void* const* d_in, const int* in_sizes, int n_in,
                              void* d_out, int out_size) {
    const float* h   = (const float*)d_in[0];
    const int*   adj = (const int*)d_in[1];
    const float* W   = (const float*)d_in[2];
    const float* a   = (const float*)d_in[3];
    float* out = (float*)d_out;

    cudaFuncSetAttribute(gat_k2, cudaFuncAttributeMaxDynamicSharedMemorySize,
                         65536);

    gat_k1<<<512, 256>>>(h, W, a);

    cudaLaunchConfig_t cfg = {};
    cfg.gridDim  = dim3(128, 1, 1);
    cfg.blockDim = dim3(512, 1, 1);
    cfg.dynamicSmemBytes = 65536;
    cfg.stream = 0;
    cudaLaunchAttribute attrs[1];
    attrs[0].id = cudaLaunchAttributeProgrammaticStreamSerialization;
    attrs[0].val.programmaticStreamSerializationAllowed = 1;
    cfg.attrs = attrs;
    cfg.numAttrs = 1;
    cudaLaunchKernelEx(&cfg, gat_k2, adj, (float*)out);
}